// round 7
// baseline (speedup 1.0000x reference)
#include <cuda_runtime.h>
#include <cuda_fp16.h>
#include <cstdint>

// ============================================================================
// Problem constants
// ============================================================================
#define T_TOKENS 4096
#define IN_F     4096
#define OUT_F    4096
#define NNZ      512

// GEMM: persistent split-K=2. 2048 work items = (tile, khalf); 296 persistent
// CTAs (2/SM x 148), round-robin items, one continuous 3-stage mbarrier ring.
static constexpr int BM = 128;
static constexpr int BN = 128;
static constexpr int BK = 64;                 // fp16 -> 128B rows (SW128 atom)
static constexpr int TILES = (T_TOKENS / BM) * (OUT_F / BN);  // 1024
static constexpr int NITEMS = 2 * TILES;                      // 2048
static constexpr int KSPLIT = IN_F / 2;                       // 2048
static constexpr int KIT = KSPLIT / BK;                       // 32 iters/item
static constexpr int NCTA = 296;                              // 2 x 148
static constexpr int STAGES = 3;
static constexpr int STAGE_BYTES = (BM * BK + BN * BK) * 2;   // 32768
static constexpr int MBAR_BASE  = STAGES * STAGE_BYTES;       // 98304
static constexpr int SMEM_TOTAL = MBAR_BASE + 64;

// fused prep kernel split
static constexpr int CONV_BLOCKS = (T_TOKENS * IN_F / 4) / 256;  // 16384

// ============================================================================
// Scratch (device globals — no allocation allowed)
// ============================================================================
__device__ __align__(16) __half g_xh[(size_t)T_TOKENS * IN_F];  // 32 MB fp16 x
__device__ __align__(16) __half g_wh[(size_t)OUT_F * IN_F];     // 32 MB fp16 dense W
__device__ int g_flag[TILES];  // split-0 done counters (256 lanes), cleared in k_prep

// ============================================================================
// Helpers
// ============================================================================
__device__ __forceinline__ uint32_t smem_u32(const void* p) {
    uint32_t a;
    asm("{ .reg .u64 t; cvta.to.shared.u64 t, %1; cvt.u32.u64 %0, t; }"
        : "=r"(a) : "l"(p));
    return a;
}
#define SW128(o) ((o) ^ (((o) >> 3) & 0x70))

__device__ __forceinline__ void cp_async16(uint32_t dst, const void* src) {
    asm volatile("cp.async.cg.shared.global [%0], [%1], 16;" :: "r"(dst), "l"(src));
}
__device__ __forceinline__ void cp_async_mbar_arrive(uint32_t mbar) {
    asm volatile("cp.async.mbarrier.arrive.noinc.shared.b64 [%0];"
                 :: "r"(mbar) : "memory");
}
__device__ __forceinline__ void mbar_init(uint32_t mbar, uint32_t cnt) {
    asm volatile("mbarrier.init.shared.b64 [%0], %1;" :: "r"(mbar), "r"(cnt)
                 : "memory");
}
__device__ __forceinline__ void mbar_arrive(uint32_t mbar) {
    asm volatile("mbarrier.arrive.release.cta.shared::cta.b64 _, [%0];"
                 :: "r"(mbar) : "memory");
}
__device__ __forceinline__ void mbar_wait(uint32_t mbar, uint32_t parity) {
    uint32_t done;
    asm volatile("{ .reg .pred p;\n\t"
        "mbarrier.try_wait.parity.acquire.cta.shared::cta.b64 p, [%1], %2;\n\t"
        "selp.b32 %0, 1, 0, p; }"
        : "=r"(done) : "r"(mbar), "r"(parity) : "memory");
    if (!done) {
        asm volatile("{ .reg .pred P1;\n\t"
            "WAIT_LOOP_%=:\n\t"
            "mbarrier.try_wait.parity.acquire.cta.shared::cta.b64 P1, [%0], %1, 0x989680;\n\t"
            "@P1 bra.uni WAIT_DONE_%=;\n\t"
            "bra.uni WAIT_LOOP_%=;\n\t"
            "WAIT_DONE_%=: }"
            :: "r"(mbar), "r"(parity) : "memory");
    }
}
__device__ __forceinline__ void ldmatrix_x4(uint32_t* r, uint32_t addr) {
    asm volatile("ldmatrix.sync.aligned.m8n8.x4.shared.b16 {%0,%1,%2,%3}, [%4];"
                 : "=r"(r[0]), "=r"(r[1]), "=r"(r[2]), "=r"(r[3]) : "r"(addr));
}
__device__ __forceinline__ void mma16816(float* c, const uint32_t* a,
                                         uint32_t b0, uint32_t b1) {
    asm volatile(
        "mma.sync.aligned.m16n8k16.row.col.f32.f16.f16.f32 "
        "{%0,%1,%2,%3}, {%4,%5,%6,%7}, {%8,%9}, {%0,%1,%2,%3};"
        : "+f"(c[0]), "+f"(c[1]), "+f"(c[2]), "+f"(c[3])
        : "r"(a[0]), "r"(a[1]), "r"(a[2]), "r"(a[3]), "r"(b0), "r"(b1));
}
__device__ __forceinline__ void red_release_add(int* p) {
    asm volatile("red.release.gpu.global.add.s32 [%0], 1;" :: "l"(p) : "memory");
}
__device__ __forceinline__ int ld_acquire_gpu(const int* p) {
    int v;
    asm volatile("ld.acquire.gpu.global.b32 %0, [%1];" : "=r"(v) : "l"(p) : "memory");
    return v;
}

// ============================================================================
// Kernel 1 (fused prep): convert x fp32->fp16; densify W rows; clear flags.
// ============================================================================
__global__ void __launch_bounds__(256) k_prep(const float4* __restrict__ x,
                                              const float* __restrict__ w,
                                              const int* __restrict__ mask) {
    if (blockIdx.x >= CONV_BLOCKS + OUT_F) {  // flag-clear block
        #pragma unroll
        for (int i = 0; i < TILES / 256; ++i)
            g_flag[threadIdx.x + i * 256] = 0;
        return;
    }
    if (blockIdx.x < CONV_BLOCKS) {
        size_t i = (size_t)blockIdx.x * 256 + threadIdx.x;
        float4 v = x[i];
        __half2* xh2 = reinterpret_cast<__half2*>(g_xh);
        xh2[2 * i]     = __floats2half2_rn(v.x, v.y);
        xh2[2 * i + 1] = __floats2half2_rn(v.z, v.w);
        return;
    }
    // ---- densify: indices sorted per row; duplicate runs summed in fp32 by
    // the run-leader thread — deterministic, no atomics.
    __shared__ float acc[IN_F];
    const int o = blockIdx.x - CONV_BLOCKS;
    const int tid = threadIdx.x;
    for (int j = tid; j < IN_F; j += 256) acc[j] = 0.0f;
    __syncthreads();

    const int* mrow = mask + (size_t)o * NNZ;
    const float* wrow = w + (size_t)o * NNZ;
    for (int j = tid; j < NNZ; j += 256) {
        int m = mrow[j];
        if (j > 0 && mrow[j - 1] == m) continue;  // not the run leader
        float s = wrow[j];
        int jj = j + 1;
        while (jj < NNZ && mrow[jj] == m) { s += wrow[jj]; jj++; }
        acc[m] = s;  // unique owner, acc pre-zeroed
    }
    __syncthreads();

    __half2* dst = reinterpret_cast<__half2*>(g_wh + (size_t)o * IN_F);
    for (int j = tid; j < IN_F / 2; j += 256)
        dst[j] = __floats2half2_rn(acc[2 * j], acc[2 * j + 1]);
}

// ============================================================================
// Kernel 2: persistent split-K=2 fp16 mma.sync GEMM.
// Item it: split = it>>10, tile = it&1023. CTA c owns items c, c+296, ...
// One continuous mbarrier ring across all items -> next item's tiles are
// prefetched while current item finishes (no per-item pipeline refill).
// Epilogue is warp-autonomous: split-0 lanes red.release.add the tile flag
// (target 256); split-1 lanes acquire-spin to 256 then RMW out. Partner
// split-0 item is ~3.4 item-positions earlier and all CTAs are co-resident,
// so spins terminate (and essentially never engage).
// ============================================================================
__global__ void __launch_bounds__(256, 2) k_gemm(const float* __restrict__ bias,
                                                 float* __restrict__ out) {
    extern __shared__ char smem[];
    const uint32_t sbase = smem_u32(smem);
    const int tid  = threadIdx.x;
    const int wid  = tid >> 5;
    const int lane = tid & 31;
    const int wm = (wid >> 2) * 64;
    const int wn = (wid & 3) * 32;
    const int cta = blockIdx.x;

    const int my_items = (NITEMS - cta + NCTA - 1) / NCTA;  // 6 or 7
    const int QTOT = my_items * KIT;

    const uint32_t mb_full0  = sbase + MBAR_BASE;
    const uint32_t mb_empty0 = sbase + MBAR_BASE + 24;

    if (tid == 0) {
        #pragma unroll
        for (int s = 0; s < STAGES; ++s) {
            mbar_init(mb_full0 + s * 8, 256);
            mbar_init(mb_empty0 + s * 8, 256);
        }
    }
    __syncthreads();

    const int ldrow = tid >> 3;
    const int ldc   = (tid & 7) * 16;
    const size_t gkc = (size_t)(ldc >> 1);

    // load stage for global iteration q (maps q -> item -> addresses)
    auto load_stage = [&](int q, int s) {
        const int it    = cta + (q >> 5) * NCTA;
        const int tile  = it & (TILES - 1);
        const int split = it >> 10;
        const size_t koff = (size_t)split * KSPLIT + (size_t)(q & 31) * BK + gkc;
        const __half* ga = g_xh + (size_t)((tile & 31) * BM) * IN_F + koff;
        const __half* gb = g_wh + (size_t)((tile >> 5) * BN) * IN_F + koff;
        const uint32_t sA = sbase + s * STAGE_BYTES;
        const uint32_t sB = sA + BM * BK * 2;
        #pragma unroll
        for (int i = 0; i < 4; ++i) {
            const int row = ldrow + i * 32;
            const uint32_t off = SW128(row * 128 + ldc);
            cp_async16(sA + off, ga + (size_t)row * IN_F);
            cp_async16(sB + off, gb + (size_t)row * IN_F);
        }
        cp_async_mbar_arrive(mb_full0 + s * 8);
    };

    #pragma unroll
    for (int s = 0; s < STAGES; ++s) load_stage(s, s);

    float acc[4][4][4];
    #pragma unroll
    for (int i = 0; i < 4; ++i)
        #pragma unroll
        for (int j = 0; j < 4; ++j)
            #pragma unroll
            for (int k = 0; k < 4; ++k) acc[i][j][k] = 0.0f;

    const int a_m  = wm + (lane & 15);
    const int a_kb = (lane >> 4) * 16;
    const int b_n  = wn + (lane & 7) + ((lane >> 4) << 3);
    const int b_kb = ((lane >> 3) & 1) * 16;

    for (int q = 0; q < QTOT; ++q) {
        const int cs = q % 3;
        const uint32_t ph = (uint32_t)(q / 3) & 1;
        mbar_wait(mb_full0 + cs * 8, ph);

        const uint32_t sA = sbase + cs * STAGE_BYTES;
        const uint32_t sB = sA + BM * BK * 2;

        #pragma unroll
        for (int ks = 0; ks < BK / 16; ++ks) {
            const int kb = ks * 32;
            uint32_t af[4][4];
            #pragma unroll
            for (int tm = 0; tm < 4; ++tm)
                ldmatrix_x4(af[tm], sA + SW128((a_m + tm * 16) * 128 + kb + a_kb));
            uint32_t bf[2][4];
            #pragma unroll
            for (int tn2 = 0; tn2 < 2; ++tn2)
                ldmatrix_x4(bf[tn2], sB + SW128((b_n + tn2 * 16) * 128 + kb + b_kb));
            if (ks == BK / 16 - 1)
                mbar_arrive(mb_empty0 + cs * 8);
            #pragma unroll
            for (int tm = 0; tm < 4; ++tm)
                #pragma unroll
                for (int tn = 0; tn < 4; ++tn)
                    mma16816(acc[tm][tn], af[tm], bf[tn >> 1][(tn & 1) * 2],
                             bf[tn >> 1][(tn & 1) * 2 + 1]);
        }

        // producer: refill this stage for iteration q+3 (possibly next item)
        if (q + 3 < QTOT) {
            mbar_wait(mb_empty0 + cs * 8, ph);
            load_stage(q + 3, cs);
        }

        // ---- item boundary: epilogue + acc reset (warp-autonomous) ----
        if ((q & 31) == 31) {
            const int it    = cta + (q >> 5) * NCTA;
            const int tile  = it & (TILES - 1);
            const int split = it >> 10;
            const int tok0  = (tile & 31) * BM;
            const int o0    = (tile >> 5) * BN;

            if (split == 0) {
                #pragma unroll
                for (int tm = 0; tm < 4; ++tm) {
                    const int row = tok0 + wm + tm * 16 + (lane >> 2);
                    #pragma unroll
                    for (int tn = 0; tn < 4; ++tn) {
                        const int col = o0 + wn + tn * 8 + 2 * (lane & 3);
                        const float2 bv = *reinterpret_cast<const float2*>(bias + col);
                        float2 v0 = {acc[tm][tn][0] + bv.x, acc[tm][tn][1] + bv.y};
                        float2 v1 = {acc[tm][tn][2] + bv.x, acc[tm][tn][3] + bv.y};
                        *reinterpret_cast<float2*>(out + (size_t)row * OUT_F + col) = v0;
                        *reinterpret_cast<float2*>(out + (size_t)(row + 8) * OUT_F + col) = v1;
                    }
                }
                red_release_add(&g_flag[tile]);  // every lane: +1 (release)
            } else {
                // every lane acquires independently -> its later reads are ordered
                while (ld_acquire_gpu(&g_flag[tile]) < 256) {
                    asm volatile("nanosleep.u32 64;");
                }
                #pragma unroll
                for (int tm = 0; tm < 4; ++tm) {
                    const int row = tok0 + wm + tm * 16 + (lane >> 2);
                    #pragma unroll
                    for (int tn = 0; tn < 4; ++tn) {
                        const int col = o0 + wn + tn * 8 + 2 * (lane & 3);
                        float* p0 = out + (size_t)row * OUT_F + col;
                        float* p1 = out + (size_t)(row + 8) * OUT_F + col;
                        float2 o0v = *reinterpret_cast<float2*>(p0);
                        float2 o1v = *reinterpret_cast<float2*>(p1);
                        o0v.x += acc[tm][tn][0]; o0v.y += acc[tm][tn][1];
                        o1v.x += acc[tm][tn][2]; o1v.y += acc[tm][tn][3];
                        *reinterpret_cast<float2*>(p0) = o0v;
                        *reinterpret_cast<float2*>(p1) = o1v;
                    }
                }
            }
            #pragma unroll
            for (int i = 0; i < 4; ++i)
                #pragma unroll
                for (int j2 = 0; j2 < 4; ++j2)
                    #pragma unroll
                    for (int k = 0; k < 4; ++k) acc[i][j2][k] = 0.0f;
        }
    }
}

// ============================================================================
// Launch
// ============================================================================
extern "C" void kernel_launch(void* const* d_in, const int* in_sizes, int n_in,
                              void* d_out, int out_size) {
    const float* x    = (const float*)d_in[0];
    const float* w    = (const float*)d_in[1];
    const int*   mask = (const int*)d_in[2];
    const float* bias = (const float*)d_in[3];
    float* out = (float*)d_out;

    cudaFuncSetAttribute(k_gemm, cudaFuncAttributeMaxDynamicSharedMemorySize,
                         SMEM_TOTAL);

    k_prep<<<CONV_BLOCKS + OUT_F + 1, 256>>>((const float4*)x, w, mask);
    k_gemm<<<NCTA, 256, SMEM_TOTAL>>>(bias, out);
}

// round 8
// speedup vs baseline: 1.0811x; 1.0811x over previous
#include <cuda_runtime.h>
#include <cuda_fp16.h>
#include <cstdint>

// ============================================================================
// Problem constants
// ============================================================================
#define T_TOKENS 4096
#define IN_F     4096
#define OUT_F    4096
#define NNZ      512

// GEMM tiling: CTA 128x128, warp tile 64x32 (8 warps, 2x4), 2 CTAs/SM.
// Tail split-K: first UNSPLIT tiles run full K (3 exact waves of 296);
// the last 136 tiles are split 2-way in K -> 272 half-items that fill the
// final wave at half duration (all co-resident: 272 < 296).
static constexpr int BM = 128;
static constexpr int BN = 128;
static constexpr int BK = 64;                 // fp16 -> 128B rows (SW128 atom)
static constexpr int TILES = (T_TOKENS / BM) * (OUT_F / BN);  // 1024
static constexpr int NCTA_WAVE = 296;                         // 2/SM x 148
static constexpr int UNSPLIT = 3 * NCTA_WAVE;                 // 888
static constexpr int NSPLIT_TILES = TILES - UNSPLIT;          // 136
static constexpr int GRID = UNSPLIT + 2 * NSPLIT_TILES;       // 1160
static constexpr int KSPLIT = IN_F / 2;                       // 2048
static constexpr int STAGES = 3;
static constexpr int STAGE_BYTES = (BM * BK + BN * BK) * 2;   // 32768
static constexpr int MBAR_BASE  = STAGES * STAGE_BYTES;       // 98304
static constexpr int SMEM_TOTAL = MBAR_BASE + 64;

// fused prep kernel split
static constexpr int CONV_BLOCKS = (T_TOKENS * IN_F / 4) / 256;  // 16384

// ============================================================================
// Scratch (device globals — no allocation allowed)
// ============================================================================
__device__ __align__(16) __half g_xh[(size_t)T_TOKENS * IN_F];  // 32 MB fp16 x
__device__ __align__(16) __half g_wh[(size_t)OUT_F * IN_F];     // 32 MB fp16 dense W
__device__ int g_flag[NSPLIT_TILES];  // split-0-done flags, cleared each launch

// ============================================================================
// Helpers
// ============================================================================
__device__ __forceinline__ uint32_t smem_u32(const void* p) {
    uint32_t a;
    asm("{ .reg .u64 t; cvta.to.shared.u64 t, %1; cvt.u32.u64 %0, t; }"
        : "=r"(a) : "l"(p));
    return a;
}
#define SW128(o) ((o) ^ (((o) >> 3) & 0x70))

__device__ __forceinline__ void cp_async16(uint32_t dst, const void* src) {
    asm volatile("cp.async.cg.shared.global [%0], [%1], 16;" :: "r"(dst), "l"(src));
}
__device__ __forceinline__ void cp_async_mbar_arrive(uint32_t mbar) {
    asm volatile("cp.async.mbarrier.arrive.noinc.shared.b64 [%0];"
                 :: "r"(mbar) : "memory");
}
__device__ __forceinline__ void mbar_init(uint32_t mbar, uint32_t cnt) {
    asm volatile("mbarrier.init.shared.b64 [%0], %1;" :: "r"(mbar), "r"(cnt)
                 : "memory");
}
__device__ __forceinline__ void mbar_arrive(uint32_t mbar) {
    asm volatile("mbarrier.arrive.release.cta.shared::cta.b64 _, [%0];"
                 :: "r"(mbar) : "memory");
}
__device__ __forceinline__ void mbar_wait(uint32_t mbar, uint32_t parity) {
    uint32_t done;
    asm volatile("{ .reg .pred p;\n\t"
        "mbarrier.try_wait.parity.acquire.cta.shared::cta.b64 p, [%1], %2;\n\t"
        "selp.b32 %0, 1, 0, p; }"
        : "=r"(done) : "r"(mbar), "r"(parity) : "memory");
    if (!done) {
        asm volatile("{ .reg .pred P1;\n\t"
            "WAIT_LOOP_%=:\n\t"
            "mbarrier.try_wait.parity.acquire.cta.shared::cta.b64 P1, [%0], %1, 0x989680;\n\t"
            "@P1 bra.uni WAIT_DONE_%=;\n\t"
            "bra.uni WAIT_LOOP_%=;\n\t"
            "WAIT_DONE_%=: }"
            :: "r"(mbar), "r"(parity) : "memory");
    }
}
__device__ __forceinline__ void ldmatrix_x4(uint32_t* r, uint32_t addr) {
    asm volatile("ldmatrix.sync.aligned.m8n8.x4.shared.b16 {%0,%1,%2,%3}, [%4];"
                 : "=r"(r[0]), "=r"(r[1]), "=r"(r[2]), "=r"(r[3]) : "r"(addr));
}
__device__ __forceinline__ void mma16816(float* c, const uint32_t* a,
                                         uint32_t b0, uint32_t b1) {
    asm volatile(
        "mma.sync.aligned.m16n8k16.row.col.f32.f16.f16.f32 "
        "{%0,%1,%2,%3}, {%4,%5,%6,%7}, {%8,%9}, {%0,%1,%2,%3};"
        : "+f"(c[0]), "+f"(c[1]), "+f"(c[2]), "+f"(c[3])
        : "r"(a[0]), "r"(a[1]), "r"(a[2]), "r"(a[3]), "r"(b0), "r"(b1));
}
__device__ __forceinline__ void st_release_gpu(int* p, int v) {
    asm volatile("st.release.gpu.global.b32 [%0], %1;" :: "l"(p), "r"(v) : "memory");
}
__device__ __forceinline__ int ld_acquire_gpu(const int* p) {
    int v;
    asm volatile("ld.acquire.gpu.global.b32 %0, [%1];" : "=r"(v) : "l"(p) : "memory");
    return v;
}

// ============================================================================
// Kernel 1 (fused prep): convert x fp32->fp16; densify W rows; clear flags.
// ============================================================================
__global__ void __launch_bounds__(256) k_prep(const float4* __restrict__ x,
                                              const float* __restrict__ w,
                                              const int* __restrict__ mask) {
    if (blockIdx.x >= CONV_BLOCKS + OUT_F) {  // flag-clear block
        if (threadIdx.x < NSPLIT_TILES) g_flag[threadIdx.x] = 0;
        return;
    }
    if (blockIdx.x < CONV_BLOCKS) {
        size_t i = (size_t)blockIdx.x * 256 + threadIdx.x;
        float4 v = x[i];
        __half2* xh2 = reinterpret_cast<__half2*>(g_xh);
        xh2[2 * i]     = __floats2half2_rn(v.x, v.y);
        xh2[2 * i + 1] = __floats2half2_rn(v.z, v.w);
        return;
    }
    // ---- densify: indices sorted per row; duplicate runs summed in fp32 by
    // the run-leader thread — deterministic, no atomics.
    __shared__ float acc[IN_F];
    const int o = blockIdx.x - CONV_BLOCKS;
    const int tid = threadIdx.x;
    for (int j = tid; j < IN_F; j += 256) acc[j] = 0.0f;
    __syncthreads();

    const int* mrow = mask + (size_t)o * NNZ;
    const float* wrow = w + (size_t)o * NNZ;
    for (int j = tid; j < NNZ; j += 256) {
        int m = mrow[j];
        if (j > 0 && mrow[j - 1] == m) continue;  // not the run leader
        float s = wrow[j];
        int jj = j + 1;
        while (jj < NNZ && mrow[jj] == m) { s += wrow[jj]; jj++; }
        acc[m] = s;  // unique owner, acc pre-zeroed
    }
    __syncthreads();

    __half2* dst = reinterpret_cast<__half2*>(g_wh + (size_t)o * IN_F);
    for (int j = tid; j < IN_F / 2; j += 256)
        dst[j] = __floats2half2_rn(acc[2 * j], acc[2 * j + 1]);
}

// ============================================================================
// Kernel 2: pipelined fp16 mma.sync GEMM, mbarrier ring, tail split-K.
//   bid < 888           : tile bid, full K (identical to the R5 fast path)
//   bid = 888 + 2t + s  : tile 888+t, K-half s (32 iters); split 0 stores
//                         partial+bias then releases flag; split 1 computes,
//                         acquire-spins the flag, then RMW-adds.
// All 272 split items land in the final wave (272 < 296 co-resident), and
// split-0 has the lower bid of each pair, so the handshake terminates.
// ============================================================================
__global__ void __launch_bounds__(256, 2) k_gemm(const float* __restrict__ bias,
                                                 float* __restrict__ out) {
    extern __shared__ char smem[];
    const uint32_t sbase = smem_u32(smem);
    const int tid  = threadIdx.x;
    const int wid  = tid >> 5;
    const int lane = tid & 31;
    const int wm = (wid >> 2) * 64;
    const int wn = (wid & 3) * 32;

    // ---- bid -> work mapping
    const int bid = blockIdx.x;
    int tile, split, kit;
    if (bid < UNSPLIT) {
        tile = bid; split = 0; kit = IN_F / BK;      // 64
    } else {
        const int s = bid - UNSPLIT;
        tile = UNSPLIT + (s >> 1); split = s & 1; kit = KSPLIT / BK;  // 32
    }
    const bool is_split = (bid >= UNSPLIT);
    const int tok0 = (tile & 31) * BM;
    const int o0   = (tile >> 5) * BN;
    const size_t kbase = (size_t)split * KSPLIT;

    const uint32_t mb_full0  = sbase + MBAR_BASE;
    const uint32_t mb_empty0 = sbase + MBAR_BASE + 24;

    if (tid == 0) {
        #pragma unroll
        for (int s = 0; s < STAGES; ++s) {
            mbar_init(mb_full0 + s * 8, 256);
            mbar_init(mb_empty0 + s * 8, 256);
        }
    }
    __syncthreads();

    const __half* ga = g_xh + (size_t)tok0 * IN_F + kbase;
    const __half* gb = g_wh + (size_t)o0 * IN_F + kbase;

    const int ldrow = tid >> 3;
    const int ldc   = (tid & 7) * 16;
    const size_t gkc = (size_t)(ldc >> 1);

    auto load_stage = [&](int it, int s) {
        const uint32_t sA = sbase + s * STAGE_BYTES;
        const uint32_t sB = sA + BM * BK * 2;
        const size_t gk = (size_t)it * BK + gkc;
        #pragma unroll
        for (int i = 0; i < 4; ++i) {
            const int row = ldrow + i * 32;
            const uint32_t off = SW128(row * 128 + ldc);
            cp_async16(sA + off, ga + (size_t)row * IN_F + gk);
            cp_async16(sB + off, gb + (size_t)row * IN_F + gk);
        }
        cp_async_mbar_arrive(mb_full0 + s * 8);
    };

    #pragma unroll
    for (int s = 0; s < STAGES; ++s) load_stage(s, s);

    float acc[4][4][4];
    #pragma unroll
    for (int i = 0; i < 4; ++i)
        #pragma unroll
        for (int j = 0; j < 4; ++j)
            #pragma unroll
            for (int k = 0; k < 4; ++k) acc[i][j][k] = 0.0f;

    const int a_m  = wm + (lane & 15);
    const int a_kb = (lane >> 4) * 16;
    const int b_n  = wn + (lane & 7) + ((lane >> 4) << 3);
    const int b_kb = ((lane >> 3) & 1) * 16;

    for (int j = 0; j < kit; ++j) {
        const int cs = j % 3;
        const uint32_t ph = (uint32_t)(j / 3) & 1;
        mbar_wait(mb_full0 + cs * 8, ph);

        const uint32_t sA = sbase + cs * STAGE_BYTES;
        const uint32_t sB = sA + BM * BK * 2;

        #pragma unroll
        for (int ks = 0; ks < BK / 16; ++ks) {
            const int kb = ks * 32;
            uint32_t af[4][4];
            #pragma unroll
            for (int tm = 0; tm < 4; ++tm)
                ldmatrix_x4(af[tm], sA + SW128((a_m + tm * 16) * 128 + kb + a_kb));
            uint32_t bf[2][4];
            #pragma unroll
            for (int tn2 = 0; tn2 < 2; ++tn2)
                ldmatrix_x4(bf[tn2], sB + SW128((b_n + tn2 * 16) * 128 + kb + b_kb));
            if (ks == BK / 16 - 1)
                mbar_arrive(mb_empty0 + cs * 8);
            #pragma unroll
            for (int tm = 0; tm < 4; ++tm)
                #pragma unroll
                for (int tn = 0; tn < 4; ++tn)
                    mma16816(acc[tm][tn], af[tm], bf[tn >> 1][(tn & 1) * 2],
                             bf[tn >> 1][(tn & 1) * 2 + 1]);
        }

        if (j + 3 < kit) {
            mbar_wait(mb_empty0 + cs * 8, ph);
            load_stage(j + 3, cs);
        }
    }

    // ---- Epilogue ----
    if (!is_split || split == 0) {
        // full tiles and split-0: partial(+bias) -> out
        #pragma unroll
        for (int tm = 0; tm < 4; ++tm) {
            const int row = tok0 + wm + tm * 16 + (lane >> 2);
            #pragma unroll
            for (int tn = 0; tn < 4; ++tn) {
                const int col = o0 + wn + tn * 8 + 2 * (lane & 3);
                const float2 bv = *reinterpret_cast<const float2*>(bias + col);
                float2 v0 = {acc[tm][tn][0] + bv.x, acc[tm][tn][1] + bv.y};
                float2 v1 = {acc[tm][tn][2] + bv.x, acc[tm][tn][3] + bv.y};
                *reinterpret_cast<float2*>(out + (size_t)row * OUT_F + col) = v0;
                *reinterpret_cast<float2*>(out + (size_t)(row + 8) * OUT_F + col) = v1;
            }
        }
        if (is_split) {
            __syncthreads();  // all stores of this CTA done
            if (tid == 0) st_release_gpu(&g_flag[tile - UNSPLIT], 1);
        }
    } else {
        // split-1: wait for split-0's stores, then accumulate into out
        if (tid == 0) {
            while (ld_acquire_gpu(&g_flag[tile - UNSPLIT]) == 0) {
                asm volatile("nanosleep.u32 64;");
            }
        }
        __syncthreads();  // flag acquire visible to whole CTA
        #pragma unroll
        for (int tm = 0; tm < 4; ++tm) {
            const int row = tok0 + wm + tm * 16 + (lane >> 2);
            #pragma unroll
            for (int tn = 0; tn < 4; ++tn) {
                const int col = o0 + wn + tn * 8 + 2 * (lane & 3);
                float* p0 = out + (size_t)row * OUT_F + col;
                float* p1 = out + (size_t)(row + 8) * OUT_F + col;
                float2 o0v = *reinterpret_cast<float2*>(p0);
                float2 o1v = *reinterpret_cast<float2*>(p1);
                o0v.x += acc[tm][tn][0]; o0v.y += acc[tm][tn][1];
                o1v.x += acc[tm][tn][2]; o1v.y += acc[tm][tn][3];
                *reinterpret_cast<float2*>(p0) = o0v;
                *reinterpret_cast<float2*>(p1) = o1v;
            }
        }
    }
}

// ============================================================================
// Launch
// ============================================================================
extern "C" void kernel_launch(void* const* d_in, const int* in_sizes, int n_in,
                              void* d_out, int out_size) {
    const float* x    = (const float*)d_in[0];
    const float* w    = (const float*)d_in[1];
    const int*   mask = (const int*)d_in[2];
    const float* bias = (const float*)d_in[3];
    float* out = (float*)d_out;

    cudaFuncSetAttribute(k_gemm, cudaFuncAttributeMaxDynamicSharedMemorySize,
                         SMEM_TOTAL);

    k_prep<<<CONV_BLOCKS + OUT_F + 1, 256>>>((const float4*)x, w, mask);
    k_gemm<<<GRID, 256, SMEM_TOTAL>>>(bias, out);
}

// round 9
// speedup vs baseline: 1.1292x; 1.0445x over previous
#include <cuda_runtime.h>
#include <cuda_fp16.h>
#include <cstdint>

// ============================================================================
// Problem constants
// ============================================================================
#define T_TOKENS 4096
#define IN_F     4096
#define OUT_F    4096
#define NNZ      512

// GEMM tiling: CTA 128x128, warp tile 64x32 (8 warps, 2x4), 2 CTAs/SM.
static constexpr int BM = 128;
static constexpr int BN = 128;
static constexpr int BK = 64;                 // fp16 -> 128B rows (SW128 atom)
static constexpr int KITERS = IN_F / BK;      // 64
static constexpr int STAGES = 3;
static constexpr int STAGE_BYTES = (BM * BK + BN * BK) * 2;  // 32768
static constexpr int MBAR_BASE  = STAGES * STAGE_BYTES;      // 98304
static constexpr int SMEM_TOTAL = MBAR_BASE + 64;            // 98368

// prep: conversion blocks do 4 float4 each (MLP=4)
static constexpr int CONV_BLOCKS = (T_TOKENS * IN_F / 4) / (256 * 4);  // 4096

// ============================================================================
// Scratch (device globals — no allocation allowed)
// ============================================================================
__device__ __align__(16) __half g_xh[(size_t)T_TOKENS * IN_F];  // 32 MB fp16 x
__device__ __align__(16) __half g_wh[(size_t)OUT_F * IN_F];     // 32 MB fp16 dense W

// ============================================================================
// Helpers
// ============================================================================
__device__ __forceinline__ uint32_t smem_u32(const void* p) {
    uint32_t a;
    asm("{ .reg .u64 t; cvta.to.shared.u64 t, %1; cvt.u32.u64 %0, t; }"
        : "=r"(a) : "l"(p));
    return a;
}
#define SW128(o) ((o) ^ (((o) >> 3) & 0x70))

__device__ __forceinline__ void cp_async16(uint32_t dst, const void* src) {
    asm volatile("cp.async.cg.shared.global [%0], [%1], 16;" :: "r"(dst), "l"(src));
}
__device__ __forceinline__ void cp_async_mbar_arrive(uint32_t mbar) {
    asm volatile("cp.async.mbarrier.arrive.noinc.shared.b64 [%0];"
                 :: "r"(mbar) : "memory");
}
__device__ __forceinline__ void mbar_init(uint32_t mbar, uint32_t cnt) {
    asm volatile("mbarrier.init.shared.b64 [%0], %1;" :: "r"(mbar), "r"(cnt)
                 : "memory");
}
__device__ __forceinline__ void mbar_arrive(uint32_t mbar) {
    asm volatile("mbarrier.arrive.release.cta.shared::cta.b64 _, [%0];"
                 :: "r"(mbar) : "memory");
}
__device__ __forceinline__ void mbar_wait(uint32_t mbar, uint32_t parity) {
    uint32_t done;
    asm volatile("{ .reg .pred p;\n\t"
        "mbarrier.try_wait.parity.acquire.cta.shared::cta.b64 p, [%1], %2;\n\t"
        "selp.b32 %0, 1, 0, p; }"
        : "=r"(done) : "r"(mbar), "r"(parity) : "memory");
    if (!done) {
        asm volatile("{ .reg .pred P1;\n\t"
            "WAIT_LOOP_%=:\n\t"
            "mbarrier.try_wait.parity.acquire.cta.shared::cta.b64 P1, [%0], %1, 0x989680;\n\t"
            "@P1 bra.uni WAIT_DONE_%=;\n\t"
            "bra.uni WAIT_LOOP_%=;\n\t"
            "WAIT_DONE_%=: }"
            :: "r"(mbar), "r"(parity) : "memory");
    }
}
__device__ __forceinline__ void ldmatrix_x4(uint32_t* r, uint32_t addr) {
    asm volatile("ldmatrix.sync.aligned.m8n8.x4.shared.b16 {%0,%1,%2,%3}, [%4];"
                 : "=r"(r[0]), "=r"(r[1]), "=r"(r[2]), "=r"(r[3]) : "r"(addr));
}
__device__ __forceinline__ void mma16816(float* c, const uint32_t* a,
                                         uint32_t b0, uint32_t b1) {
    asm volatile(
        "mma.sync.aligned.m16n8k16.row.col.f32.f16.f16.f32 "
        "{%0,%1,%2,%3}, {%4,%5,%6,%7}, {%8,%9}, {%0,%1,%2,%3};"
        : "+f"(c[0]), "+f"(c[1]), "+f"(c[2]), "+f"(c[3])
        : "r"(a[0]), "r"(a[1]), "r"(a[2]), "r"(a[3]), "r"(b0), "r"(b1));
}

// ============================================================================
// Kernel 1 (fused prep):
//   blocks [0, CONV_BLOCKS): convert x fp32->fp16, 4 independent float4 per
//   thread (MLP=4 fully hides DRAM latency per the B300 LDG model).
//   blocks [CONV_BLOCKS, +OUT_F): densify one W row each. Mask/weight rows
//   are staged into smem (vectorized) so the duplicate-run scan hits smem.
// ============================================================================
__global__ void __launch_bounds__(256) k_prep(const float4* __restrict__ x,
                                              const float* __restrict__ w,
                                              const int* __restrict__ mask) {
    if (blockIdx.x < CONV_BLOCKS) {
        const size_t base = (size_t)blockIdx.x * (256 * 4) + threadIdx.x;
        float4 v[4];
        #pragma unroll
        for (int i = 0; i < 4; ++i) v[i] = x[base + i * 256];  // 4 loads in flight
        __half2* xh2 = reinterpret_cast<__half2*>(g_xh);
        #pragma unroll
        for (int i = 0; i < 4; ++i) {
            const size_t idx = base + i * 256;
            xh2[2 * idx]     = __floats2half2_rn(v[i].x, v[i].y);
            xh2[2 * idx + 1] = __floats2half2_rn(v[i].z, v[i].w);
        }
        return;
    }
    // ---- densify: indices sorted per row; duplicate runs summed in fp32 by
    // the run-leader thread — deterministic, no atomics.
    __shared__ float acc[IN_F];   // 16 KB
    __shared__ int   sm[NNZ];     // 2 KB staged mask row
    __shared__ float sw[NNZ];     // 2 KB staged weight row
    const int o = blockIdx.x - CONV_BLOCKS;
    const int tid = threadIdx.x;

    // stage mask/w rows (vectorized: 128 int4 + 128 float4)
    if (tid < NNZ / 4) {
        reinterpret_cast<int4*>(sm)[tid] =
            reinterpret_cast<const int4*>(mask + (size_t)o * NNZ)[tid];
        reinterpret_cast<float4*>(sw)[tid] =
            reinterpret_cast<const float4*>(w + (size_t)o * NNZ)[tid];
    }
    #pragma unroll
    for (int i = 0; i < IN_F / 256; ++i) acc[tid + i * 256] = 0.0f;
    __syncthreads();

    #pragma unroll
    for (int jb = 0; jb < NNZ / 256; ++jb) {
        const int j = tid + jb * 256;
        const int m = sm[j];
        if (j > 0 && sm[j - 1] == m) continue;  // not the run leader
        float s = sw[j];
        int jj = j + 1;
        while (jj < NNZ && sm[jj] == m) { s += sw[jj]; jj++; }
        acc[m] = s;  // unique owner, acc pre-zeroed
    }
    __syncthreads();

    __half2* dst = reinterpret_cast<__half2*>(g_wh + (size_t)o * IN_F);
    #pragma unroll
    for (int i = 0; i < IN_F / 512; ++i) {
        const int j = tid + i * 256;
        dst[j] = __floats2half2_rn(acc[2 * j], acc[2 * j + 1]);
    }
}

// ============================================================================
// Kernel 2: pipelined fp16 mma.sync GEMM (R5 configuration — best measured).
//   out[T,O] = xh[T,In] * Wh[O,In]^T + bias
// CTA 128x128, BK=64, 3-stage mbarrier ring, 8 warps @ 64x32, 2 CTAs/SM.
// full[s] tracks cp.async completion; empty[s] tracks all-warps-done-reading.
// Warps drift up to ~1 iteration, desynchronizing LDSM bursts so the tensor
// pipe stays fed through the load windows.
// ============================================================================
__global__ void __launch_bounds__(256, 2) k_gemm(const float* __restrict__ bias,
                                                 float* __restrict__ out) {
    extern __shared__ char smem[];
    const uint32_t sbase = smem_u32(smem);
    const int tid  = threadIdx.x;
    const int wid  = tid >> 5;
    const int lane = tid & 31;
    const int wm = (wid >> 2) * 64;   // warp row offset
    const int wn = (wid & 3) * 32;    // warp col offset
    const int tok0 = blockIdx.x * BM;
    const int o0   = blockIdx.y * BN;

    const uint32_t mb_full0  = sbase + MBAR_BASE;
    const uint32_t mb_empty0 = sbase + MBAR_BASE + 24;

    if (tid == 0) {
        #pragma unroll
        for (int s = 0; s < STAGES; ++s) {
            mbar_init(mb_full0 + s * 8, 256);
            mbar_init(mb_empty0 + s * 8, 256);
        }
    }
    __syncthreads();  // barriers visible before any use

    const __half* ga = g_xh + (size_t)tok0 * IN_F;
    const __half* gb = g_wh + (size_t)o0 * IN_F;

    const int ldrow = tid >> 3;        // 0..31
    const int ldc   = (tid & 7) * 16;  // byte offset within 128B row
    const size_t gkc = (size_t)(ldc >> 1);

    auto load_stage = [&](int it, int s) {
        const uint32_t sA = sbase + s * STAGE_BYTES;
        const uint32_t sB = sA + BM * BK * 2;
        const size_t gk = (size_t)it * BK + gkc;
        #pragma unroll
        for (int i = 0; i < 4; ++i) {
            const int row = ldrow + i * 32;
            const uint32_t off = SW128(row * 128 + ldc);
            cp_async16(sA + off, ga + (size_t)row * IN_F + gk);
            cp_async16(sB + off, gb + (size_t)row * IN_F + gk);
        }
        cp_async_mbar_arrive(mb_full0 + s * 8);
    };

    #pragma unroll
    for (int s = 0; s < STAGES; ++s) load_stage(s, s);

    float acc[4][4][4];
    #pragma unroll
    for (int i = 0; i < 4; ++i)
        #pragma unroll
        for (int j = 0; j < 4; ++j)
            #pragma unroll
            for (int k = 0; k < 4; ++k) acc[i][j][k] = 0.0f;

    const int a_m  = wm + (lane & 15);
    const int a_kb = (lane >> 4) * 16;
    const int b_n  = wn + (lane & 7) + ((lane >> 4) << 3);
    const int b_kb = ((lane >> 3) & 1) * 16;

    for (int j = 0; j < KITERS; ++j) {
        const int cs = j % 3;
        const uint32_t ph = (uint32_t)(j / 3) & 1;
        mbar_wait(mb_full0 + cs * 8, ph);

        const uint32_t sA = sbase + cs * STAGE_BYTES;
        const uint32_t sB = sA + BM * BK * 2;

        #pragma unroll
        for (int ks = 0; ks < BK / 16; ++ks) {
            const int kb = ks * 32;
            uint32_t af[4][4];
            #pragma unroll
            for (int tm = 0; tm < 4; ++tm)
                ldmatrix_x4(af[tm], sA + SW128((a_m + tm * 16) * 128 + kb + a_kb));
            uint32_t bf[2][4];
            #pragma unroll
            for (int tn2 = 0; tn2 < 2; ++tn2)
                ldmatrix_x4(bf[tn2], sB + SW128((b_n + tn2 * 16) * 128 + kb + b_kb));
            if (ks == BK / 16 - 1)
                mbar_arrive(mb_empty0 + cs * 8);  // all my reads of stage cs done
            #pragma unroll
            for (int tm = 0; tm < 4; ++tm)
                #pragma unroll
                for (int tn = 0; tn < 4; ++tn)
                    mma16816(acc[tm][tn], af[tm], bf[tn >> 1][(tn & 1) * 2],
                             bf[tn >> 1][(tn & 1) * 2 + 1]);
        }

        if (j + 3 < KITERS) {
            mbar_wait(mb_empty0 + cs * 8, ph);  // all warps done reading stage cs
            load_stage(j + 3, cs);
        }
    }

    // ---- Epilogue: direct register -> gmem (float2), + bias
    #pragma unroll
    for (int tm = 0; tm < 4; ++tm) {
        const int row = tok0 + wm + tm * 16 + (lane >> 2);
        #pragma unroll
        for (int tn = 0; tn < 4; ++tn) {
            const int col = o0 + wn + tn * 8 + 2 * (lane & 3);
            const float2 bv = *reinterpret_cast<const float2*>(bias + col);
            float2 v0 = {acc[tm][tn][0] + bv.x, acc[tm][tn][1] + bv.y};
            float2 v1 = {acc[tm][tn][2] + bv.x, acc[tm][tn][3] + bv.y};
            *reinterpret_cast<float2*>(out + (size_t)row * OUT_F + col) = v0;
            *reinterpret_cast<float2*>(out + (size_t)(row + 8) * OUT_F + col) = v1;
        }
    }
}

// ============================================================================
// Launch
// ============================================================================
extern "C" void kernel_launch(void* const* d_in, const int* in_sizes, int n_in,
                              void* d_out, int out_size) {
    const float* x    = (const float*)d_in[0];
    const float* w    = (const float*)d_in[1];
    const int*   mask = (const int*)d_in[2];
    const float* bias = (const float*)d_in[3];
    float* out = (float*)d_out;

    cudaFuncSetAttribute(k_gemm, cudaFuncAttributeMaxDynamicSharedMemorySize,
                         SMEM_TOTAL);

    k_prep<<<CONV_BLOCKS + OUT_F, 256>>>((const float4*)x, w, mask);
    k_gemm<<<dim3(T_TOKENS / BM, OUT_F / BN), 256, SMEM_TOTAL>>>(bias, out);
}